// round 6
// baseline (speedup 1.0000x reference)
#include <cuda_runtime.h>
#include <cuda_bf16.h>
#include <cuda_fp16.h>
#include <cstdint>

#define N_ENT  100000
#define NQ     64
#define NT     100064
#define D      128
#define HD     256
#define E_EDGE 400000
#define E_TOT  500000
#define R_REL  500
#define NEG    0.2f

// ---------------- static device scratch ----------------
__device__ __align__(16) float  g_xl[(size_t)NT * HD];      // fp32 (value path)
__device__ __align__(16) __half g_xlh[(size_t)NT * HD];     // fp16 shadow (logit path)
__device__ __align__(16) __half g_xr[(size_t)NT * HD];      // fp16 (logit path)
__device__ __align__(16) __half g_erel[(R_REL + 1) * HD];   // fp16 (logit path)
__device__ float g_p[(size_t)E_TOT * 2];
__device__ float g_den[(size_t)N_ENT * 2];
__device__ __nv_bfloat16 g_wh[512 * 128];   // [outcol n][k] bf16 hi
__device__ __nv_bfloat16 g_wl[512 * 128];   // bf16 lo residual

// ---------------- helpers ----------------
__device__ __forceinline__ uint32_t smem_u32(const void* p) {
    uint32_t a;
    asm("{ .reg .u64 t; cvta.to.shared.u64 t, %1; cvt.u32.u64 %0, t; }" : "=r"(a) : "l"(p));
    return a;
}
__device__ __forceinline__ void ldsm_x4(uint32_t* r, uint32_t addr) {
    asm volatile("ldmatrix.sync.aligned.m8n8.x4.shared.b16 {%0,%1,%2,%3}, [%4];"
                 : "=r"(r[0]), "=r"(r[1]), "=r"(r[2]), "=r"(r[3]) : "r"(addr));
}
__device__ __forceinline__ void mma_bf16(float* d, const uint32_t* a, const uint32_t* b) {
    asm volatile("mma.sync.aligned.m16n8k16.row.col.f32.bf16.bf16.f32 "
                 "{%0,%1,%2,%3}, {%4,%5,%6,%7}, {%8,%9}, {%0,%1,%2,%3};"
                 : "+f"(d[0]), "+f"(d[1]), "+f"(d[2]), "+f"(d[3])
                 : "r"(a[0]), "r"(a[1]), "r"(a[2]), "r"(a[3]), "r"(b[0]), "r"(b[1]));
}
__device__ __forceinline__ void cp16(uint32_t dst, const void* src) {
    asm volatile("cp.async.cg.shared.global [%0], [%1], 16;" :: "r"(dst), "l"(src));
}
#define CPCOMMIT() asm volatile("cp.async.commit_group;" ::: "memory")
#define CPWAIT1()  asm volatile("cp.async.wait_group 1;" ::: "memory")

// XOR-swizzled planes, 256B rows: plane = 32KB
#define PLANE 32768
#define SM_AHI 0
#define SM_ALO PLANE
#define SM_B0  (2 * PLANE)
#define SM_B1  (3 * PLANE)
#define SM_TOTAL (4 * PLANE)        // 131072 B, 1 CTA/SM (512 threads)

// ---------------- split W into bf16 hi/lo ----------------
__global__ void k_wsplit(const float* __restrict__ Wl, const float* __restrict__ Wr) {
    int i = blockIdx.x * 256 + threadIdx.x;
    if (i >= 512 * 128) return;
    int n = i >> 7, k = i & 127;
    float v = (n < 256) ? Wl[n * 128 + k] : Wr[(n - 256) * 128 + k];
    __nv_bfloat16 h = __float2bfloat16(v);
    g_wh[i] = h;
    g_wl[i] = __float2bfloat16(v - __bfloat162float(h));
}

// B tile loader: 128 n-rows x 128 k bf16, 16B chunks, swizzled (512 threads)
__device__ __forceinline__ void load_b_tile(uint32_t sb, uint32_t dstoff,
                                            const __nv_bfloat16* w, int tid) {
#pragma unroll
    for (int i = 0; i < 4; ++i) {
        int j = i * 512 + tid;          // 0..2047
        int r = j >> 4, c = j & 15;
        uint32_t dst = sb + dstoff + (uint32_t)(r * 256 + ((c ^ (r & 7)) << 4));
        cp16(dst, w + r * 128 + c * 8);
    }
    CPCOMMIT();
}

// ---------------- HMMA GEMM: [x_l|x_r] = node @ [W_l;W_r].T + bias ----------------
// 512 threads, 128KB smem, double-buffered B: all loads overlapped with compute.
__global__ __launch_bounds__(512, 1) void k_gemm_mma(
    const float* __restrict__ ent, const float* __restrict__ qry,
    const float* __restrict__ bl, const float* __restrict__ br) {
    extern __shared__ char smem[];
    const uint32_t sb = smem_u32(smem);
    const int tid = threadIdx.x;
    const int wid = tid >> 5, lane = tid & 31;
    const int row0 = blockIdx.x * 128;

    load_b_tile(sb, SM_B0, g_wh, tid);   // Bh(0)
    load_b_tile(sb, SM_B1, g_wl, tid);   // Bl(0)

    // ---- A convert fp32 -> bf16 hi/lo, swizzled smem (overlaps cp.async) ----
#pragma unroll
    for (int i = 0; i < 8; ++i) {
        int idx = i * 512 + tid;            // 0..4095
        int r = idx >> 5, c4 = (idx & 31) * 4;
        int gr = row0 + r;
        float4 v = make_float4(0.f, 0.f, 0.f, 0.f);
        if (gr < N_ENT)   v = *(const float4*)(ent + (size_t)gr * D + c4);
        else if (gr < NT) v = *(const float4*)(qry + (size_t)(gr - N_ENT) * D + c4);
        float f[4] = {v.x, v.y, v.z, v.w};
        uint32_t h01 = 0, h23 = 0, l01 = 0, l23 = 0;
#pragma unroll
        for (int j = 0; j < 4; ++j) {
            __nv_bfloat16 hb = __float2bfloat16(f[j]);
            __nv_bfloat16 lb = __float2bfloat16(f[j] - __bfloat162float(hb));
            uint32_t hu = *(unsigned short*)&hb, lu = *(unsigned short*)&lb;
            if (j < 2) { h01 |= hu << (16 * j);       l01 |= lu << (16 * j); }
            else       { h23 |= hu << (16 * (j - 2)); l23 |= lu << (16 * (j - 2)); }
        }
        uint32_t off = (uint32_t)(r * 256 + (((c4 >> 3) ^ (r & 7)) << 4) + ((c4 & 4) ? 8 : 0));
        *(uint2*)(smem + SM_AHI + off) = make_uint2(h01, h23);
        *(uint2*)(smem + SM_ALO + off) = make_uint2(l01, l23);
    }
    CPWAIT1();          // Bh(0) complete (Bl(0) may be in flight)
    __syncthreads();

    const int wm = wid & 3;     // 4 m-groups of 32 rows
    const int wn = wid >> 2;    // 4 n-groups of 32 cols
    const int am = wm * 32 + (lane & 15);
    const int akc = (lane >> 4);
    const int bn = wn * 32 + ((lane >> 4) & 1) * 8 + (lane & 7);
    const int bkc = ((lane >> 3) & 1);
    const int gid = lane >> 2, tig = lane & 3;
    const uint32_t a0base = sb + SM_AHI + (uint32_t)(am * 256);
    const uint32_t a1base = sb + SM_AHI + (uint32_t)((am + 16) * 256);
    const int axor = am & 7;
    const uint32_t bbase0 = sb + SM_B0 + (uint32_t)(bn * 256);
    const int bxor = bn & 7;

    for (int t = 0; t < 4; ++t) {
        if (t > 0) {            // Bh(t) ready (only Bl(t) may remain in flight)
            CPWAIT1();
            __syncthreads();
        }

        float acc[2][4][4];
#pragma unroll
        for (int a = 0; a < 2; ++a)
#pragma unroll
            for (int b = 0; b < 4; ++b)
#pragma unroll
                for (int c = 0; c < 4; ++c) acc[a][b][c] = 0.f;

        // ---- phase 1: Ah*Bh + Al*Bh (B0) ----
#pragma unroll
        for (int ks = 0; ks < 8; ++ks) {
            uint32_t ach = (uint32_t)(((2 * ks + akc) ^ axor) << 4);
            uint32_t ah0[4], ah1[4], al0[4], al1[4];
            ldsm_x4(ah0, a0base + ach);
            ldsm_x4(al0, a0base + ach + PLANE);
            ldsm_x4(ah1, a1base + ach);
            ldsm_x4(al1, a1base + ach + PLANE);
            uint32_t kx = (uint32_t)(((2 * ks + bkc) ^ bxor) << 4);
#pragma unroll
            for (int ntp = 0; ntp < 2; ++ntp) {
                uint32_t bh[4];
                ldsm_x4(bh, bbase0 + (uint32_t)(ntp * 4096) + kx);
                mma_bf16(acc[0][2 * ntp],     ah0, bh);
                mma_bf16(acc[0][2 * ntp],     al0, bh);
                mma_bf16(acc[0][2 * ntp + 1], ah0, bh + 2);
                mma_bf16(acc[0][2 * ntp + 1], al0, bh + 2);
                mma_bf16(acc[1][2 * ntp],     ah1, bh);
                mma_bf16(acc[1][2 * ntp],     al1, bh);
                mma_bf16(acc[1][2 * ntp + 1], ah1, bh + 2);
                mma_bf16(acc[1][2 * ntp + 1], al1, bh + 2);
            }
        }
        __syncthreads();                       // B0 free
        if (t < 3) load_b_tile(sb, SM_B0, g_wh + (size_t)(t + 1) * 16384, tid);
        CPWAIT1();                             // Bl(t) ready (pending: Bh(t+1))
        __syncthreads();

        // ---- phase 2: Ah*Bl (B1) ----
#pragma unroll
        for (int ks = 0; ks < 8; ++ks) {
            uint32_t ach = (uint32_t)(((2 * ks + akc) ^ axor) << 4);
            uint32_t ah0[4], ah1[4];
            ldsm_x4(ah0, a0base + ach);
            ldsm_x4(ah1, a1base + ach);
            uint32_t kx = (uint32_t)(((2 * ks + bkc) ^ bxor) << 4);
#pragma unroll
            for (int ntp = 0; ntp < 2; ++ntp) {
                uint32_t blo[4];
                ldsm_x4(blo, bbase0 + PLANE + (uint32_t)(ntp * 4096) + kx);
                mma_bf16(acc[0][2 * ntp],     ah0, blo);
                mma_bf16(acc[0][2 * ntp + 1], ah0, blo + 2);
                mma_bf16(acc[1][2 * ntp],     ah1, blo);
                mma_bf16(acc[1][2 * ntp + 1], ah1, blo + 2);
            }
        }
        __syncthreads();                       // B1 free
        if (t < 3) load_b_tile(sb, SM_B1, g_wl + (size_t)(t + 1) * 16384, tid);

        // ---- epilogue (overlaps in-flight loads) ----
#pragma unroll
        for (int mi = 0; mi < 2; ++mi) {
            int r1 = row0 + wm * 32 + mi * 16 + gid;
            int r2 = r1 + 8;
#pragma unroll
            for (int ni = 0; ni < 4; ++ni) {
                int cg = t * 128 + wn * 32 + ni * 8 + tig * 2;   // 0..511
                if (cg < HD) {
                    float2 bv = *(const float2*)(bl + cg);
                    if (r1 < NT) {
                        float2 o = make_float2(acc[mi][ni][0] + bv.x, acc[mi][ni][1] + bv.y);
                        *(float2*)(g_xl + (size_t)r1 * HD + cg) = o;
                        *(__half2*)(g_xlh + (size_t)r1 * HD + cg) = __floats2half2_rn(o.x, o.y);
                    }
                    if (r2 < NT) {
                        float2 o = make_float2(acc[mi][ni][2] + bv.x, acc[mi][ni][3] + bv.y);
                        *(float2*)(g_xl + (size_t)r2 * HD + cg) = o;
                        *(__half2*)(g_xlh + (size_t)r2 * HD + cg) = __floats2half2_rn(o.x, o.y);
                    }
                } else {
                    int c = cg - HD;
                    float2 bv = *(const float2*)(br + c);
                    if (r1 < NT)
                        *(__half2*)(g_xr + (size_t)r1 * HD + c) =
                            __floats2half2_rn(acc[mi][ni][0] + bv.x, acc[mi][ni][1] + bv.y);
                    if (r2 < NT)
                        *(__half2*)(g_xr + (size_t)r2 * HD + c) =
                            __floats2half2_rn(acc[mi][ni][2] + bv.x, acc[mi][ni][3] + bv.y);
                }
            }
        }
    }
}

// ---------------- init ----------------
__global__ void k_init(float* __restrict__ out, const float* __restrict__ bias) {
    int i = blockIdx.x * blockDim.x + threadIdx.x;
    if (i < N_ENT * D) out[i] = bias[i & (D - 1)];
    if (i < N_ENT * 2) g_den[i] = 0.f;
}

// ---------------- fused: e_rel = rel_feat @ W_ea.T, out_edge row ----------------
__global__ void k_rel_fused(const float* __restrict__ relations, const float* __restrict__ Wea,
                            const float* __restrict__ Wle, const float* __restrict__ ble,
                            float* __restrict__ out) {
    __shared__ float row[D];
    __shared__ float hid[HD];
    __shared__ float part[256];
    int r = blockIdx.x;          // 0..500
    int tid = threadIdx.x;       // 256
    if (tid < D) row[tid] = (r == R_REL) ? 1.f : relations[r * D + tid];
    __syncthreads();
    const float4* rv = (const float4*)row;
    const float4* wv = (const float4*)(Wea + (size_t)tid * D);
    float s = 0.f;
#pragma unroll
    for (int k = 0; k < D / 4; ++k) {
        float4 a = rv[k], b = wv[k];
        s += a.x * b.x + a.y * b.y + a.z * b.z + a.w * b.w;
    }
    g_erel[r * HD + tid] = __float2half(s);
    if (r == R_REL) return;
    hid[tid] = fmaxf(s, 0.f);
    __syncthreads();

    int col = tid & 127, half = tid >> 7;
    const float4* hv = (const float4*)(hid + half * 128);
    const float4* wlv = (const float4*)(Wle + (size_t)col * HD + half * 128);
    float p = 0.f;
#pragma unroll
    for (int k = 0; k < 32; ++k) {
        float4 a = hv[k], b = wlv[k];
        p += a.x * b.x + a.y * b.y + a.z * b.z + a.w * b.w;
    }
    part[tid] = p;
    __syncthreads();
    if (tid < 128)
        out[(size_t)N_ENT * D + r * D + tid] = part[tid] + part[tid + 128] + ble[tid];
}

// ---------------- edge helpers ----------------
__device__ __forceinline__ void edge_st(int gw, const int* __restrict__ ei,
                                        const int* __restrict__ batch, int& s, int& t) {
    if (gw < E_EDGE) { s = ei[gw]; t = ei[E_EDGE + gw]; }
    else             { int i = gw - E_EDGE; s = N_ENT + batch[i]; t = i; }
}
__device__ __forceinline__ float4 leaky4(float4 z) {
    z.x = z.x > 0.f ? z.x : NEG * z.x;
    z.y = z.y > 0.f ? z.y : NEG * z.y;
    z.z = z.z > 0.f ? z.z : NEG * z.z;
    z.w = z.w > 0.f ? z.w : NEG * z.w;
    return z;
}
__device__ __forceinline__ float4 h4_to_f4(uint2 u) {
    __half2* hp = (__half2*)&u;
    float2 a = __half22float2(hp[0]), b = __half22float2(hp[1]);
    return make_float4(a.x, a.y, b.x, b.y);
}

// ---------------- edge pass 1: logits (all-fp16 gathers) ----------------
__global__ void k_logits(const int* __restrict__ ei, const int* __restrict__ ridx,
                         const int* __restrict__ batch, const float* __restrict__ att) {
    int gw = (blockIdx.x * blockDim.x + threadIdx.x) >> 5;
    if (gw >= E_TOT) return;
    int lane = threadIdx.x & 31;
    int s, t;
    edge_st(gw, ei, batch, s, t);
    int rel = (gw < E_EDGE) ? ridx[gw] : R_REL;

    const uint2*  A  = (const uint2*)g_xlh + (size_t)s * 64;
    const uint2*  Xr = (const uint2*)g_xr + (size_t)t * 64;
    const uint2*  Ee = (const uint2*)g_erel + (size_t)rel * 64;
    const float4* At = (const float4*)att;

    float4 a = h4_to_f4(A[lane]);
    float4 b = h4_to_f4(Xr[lane]);
    float4 c = h4_to_f4(Ee[lane]);
    float4 z = leaky4(make_float4(a.x + b.x + c.x, a.y + b.y + c.y,
                                  a.z + b.z + c.z, a.w + b.w + c.w));
    float4 ta = At[lane];
    float s0 = z.x * ta.x + z.y * ta.y + z.z * ta.z + z.w * ta.w;

    a = h4_to_f4(A[lane + 32]);
    b = h4_to_f4(Xr[lane + 32]);
    c = h4_to_f4(Ee[lane + 32]);
    z = leaky4(make_float4(a.x + b.x + c.x, a.y + b.y + c.y,
                           a.z + b.z + c.z, a.w + b.w + c.w));
    ta = At[lane + 32];
    float s1 = z.x * ta.x + z.y * ta.y + z.z * ta.z + z.w * ta.w;

#pragma unroll
    for (int o = 16; o; o >>= 1) {
        s0 += __shfl_xor_sync(0xffffffffu, s0, o);
        s1 += __shfl_xor_sync(0xffffffffu, s1, o);
    }
    if (lane == 0) {
        float2 pv;
        pv.x = expf(s0);
        pv.y = expf(s1);
        ((float2*)g_p)[gw] = pv;
        atomicAdd((float2*)g_den + t, pv);
    }
}

// ---------------- edge pass 2: aggregation (fp32 value path) ----------------
__global__ void k_agg(const int* __restrict__ ei, const int* __restrict__ batch,
                      float* __restrict__ out) {
    int gw = (blockIdx.x * blockDim.x + threadIdx.x) >> 5;
    if (gw >= E_TOT) return;
    int lane = threadIdx.x & 31;
    int s, t;
    edge_st(gw, ei, batch, s, t);

    float2 p  = ((const float2*)g_p)[gw];
    float2 dn = ((const float2*)g_den)[t];
    float w0 = 0.5f * p.x / (dn.x + 1e-16f);
    float w1 = 0.5f * p.y / (dn.y + 1e-16f);

    const float4* A = (const float4*)g_xl + (size_t)s * 64;
    float4 a0 = A[lane], a1 = A[lane + 32];
    float4 v = make_float4(w0 * a0.x + w1 * a1.x, w0 * a0.y + w1 * a1.y,
                           w0 * a0.z + w1 * a1.z, w0 * a0.w + w1 * a1.w);
    atomicAdd((float4*)out + (size_t)t * 32 + lane, v);
}

// ---------------- launch ----------------
extern "C" void kernel_launch(void* const* d_in, const int* in_sizes, int n_in,
                              void* d_out, int out_size) {
    const float* queries        = (const float*)d_in[0];
    const float* entities       = (const float*)d_in[1];
    const int*   edge_index     = (const int*)d_in[2];
    const float* relations      = (const float*)d_in[3];
    const int*   relation_index = (const int*)d_in[4];
    const int*   batch          = (const int*)d_in[5];
    const float* W_l  = (const float*)d_in[6];
    const float* b_l  = (const float*)d_in[7];
    const float* W_r  = (const float*)d_in[8];
    const float* b_r  = (const float*)d_in[9];
    const float* W_ea = (const float*)d_in[10];
    const float* att  = (const float*)d_in[11];
    const float* bias = (const float*)d_in[12];
    const float* W_le = (const float*)d_in[13];
    const float* b_le = (const float*)d_in[14];
    float* out = (float*)d_out;

    k_wsplit<<<(512 * 128 + 255) / 256, 256>>>(W_l, W_r);
    k_init<<<(N_ENT * D + 255) / 256, 256>>>(out, bias);
    k_rel_fused<<<R_REL + 1, 256>>>(relations, W_ea, W_le, b_le, out);

    cudaFuncSetAttribute(k_gemm_mma, cudaFuncAttributeMaxDynamicSharedMemorySize, SM_TOTAL);
    k_gemm_mma<<<(NT + 127) / 128, 512, SM_TOTAL>>>(entities, queries, b_l, b_r);

    int edge_blocks = (E_TOT * 32 + 255) / 256;
    k_logits<<<edge_blocks, 256>>>(edge_index, relation_index, batch, att);
    k_agg<<<edge_blocks, 256>>>(edge_index, batch, out);
}

// round 7
// speedup vs baseline: 1.1425x; 1.1425x over previous
#include <cuda_runtime.h>
#include <cuda_bf16.h>
#include <cuda_fp16.h>
#include <cstdint>

#define N_ENT  100000
#define NQ     64
#define NT     100064
#define D      128
#define HD     256
#define E_EDGE 400000
#define E_TOT  500000
#define R_REL  500
#define NEG    0.2f

// ---------------- static device scratch ----------------
__device__ __align__(16) __half g_xlh[(size_t)NT * HD];     // fp16 x_l (logit + value)
__device__ __align__(16) __half g_xr[(size_t)NT * HD];      // fp16 x_r (logit)
__device__ __align__(16) __half g_erel[(R_REL + 1) * HD];   // fp16 e_rel (logit)
__device__ float g_p[(size_t)E_TOT * 2];
__device__ float g_den[(size_t)N_ENT * 2];
__device__ __nv_bfloat16 g_wh[512 * 128];   // [outcol n][k] bf16 hi
__device__ __nv_bfloat16 g_wl[512 * 128];   // bf16 lo residual

// ---------------- helpers ----------------
__device__ __forceinline__ uint32_t smem_u32(const void* p) {
    uint32_t a;
    asm("{ .reg .u64 t; cvta.to.shared.u64 t, %1; cvt.u32.u64 %0, t; }" : "=r"(a) : "l"(p));
    return a;
}
__device__ __forceinline__ void ldsm_x4(uint32_t* r, uint32_t addr) {
    asm volatile("ldmatrix.sync.aligned.m8n8.x4.shared.b16 {%0,%1,%2,%3}, [%4];"
                 : "=r"(r[0]), "=r"(r[1]), "=r"(r[2]), "=r"(r[3]) : "r"(addr));
}
__device__ __forceinline__ void mma_bf16(float* d, const uint32_t* a, const uint32_t* b) {
    asm volatile("mma.sync.aligned.m16n8k16.row.col.f32.bf16.bf16.f32 "
                 "{%0,%1,%2,%3}, {%4,%5,%6,%7}, {%8,%9}, {%0,%1,%2,%3};"
                 : "+f"(d[0]), "+f"(d[1]), "+f"(d[2]), "+f"(d[3])
                 : "r"(a[0]), "r"(a[1]), "r"(a[2]), "r"(a[3]), "r"(b[0]), "r"(b[1]));
}
__device__ __forceinline__ void cp16(uint32_t dst, const void* src) {
    asm volatile("cp.async.cg.shared.global [%0], [%1], 16;" :: "r"(dst), "l"(src));
}

// XOR-swizzled planes, 256B rows: plane = 32KB
#define PLANE 32768
#define SM_AHI 0
#define SM_ALO PLANE
#define SM_B   (2 * PLANE)
#define SM_TOTAL (3 * PLANE)        // 98304 -> 2 CTAs/SM

// ---------------- split W into bf16 hi/lo ----------------
__global__ void k_wsplit(const float* __restrict__ Wl, const float* __restrict__ Wr) {
    int i = blockIdx.x * 256 + threadIdx.x;
    if (i >= 512 * 128) return;
    int n = i >> 7, k = i & 127;
    float v = (n < 256) ? Wl[n * 128 + k] : Wr[(n - 256) * 128 + k];
    __nv_bfloat16 h = __float2bfloat16(v);
    g_wh[i] = h;
    g_wl[i] = __float2bfloat16(v - __bfloat162float(h));
}

// B tile loader: 128 n-rows x 128 k bf16, 16B chunks, swizzled (256 threads)
__device__ __forceinline__ void load_b_tile(uint32_t sb, const __nv_bfloat16* w, int tid) {
#pragma unroll
    for (int i = 0; i < 8; ++i) {
        int j = i * 256 + tid;          // 0..2047
        int r = j >> 4, c = j & 15;
        uint32_t dst = sb + SM_B + (uint32_t)(r * 256 + ((c ^ (r & 7)) << 4));
        cp16(dst, w + r * 128 + c * 8);
    }
    asm volatile("cp.async.commit_group;" ::: "memory");
}
#define CPWAIT() asm volatile("cp.async.wait_group 0;" ::: "memory")

// ---------------- HMMA GEMM: [x_l|x_r] = node @ [W_l;W_r].T + bias (R5 struct) --
__global__ __launch_bounds__(256, 2) void k_gemm_mma(
    const float* __restrict__ ent, const float* __restrict__ qry,
    const float* __restrict__ bl, const float* __restrict__ br) {
    extern __shared__ char smem[];
    const uint32_t sb = smem_u32(smem);
    const int tid = threadIdx.x;
    const int wid = tid >> 5, lane = tid & 31;
    const int row0 = blockIdx.x * 128;

    load_b_tile(sb, g_wh, tid);      // prefetch Bh(0)

    // ---- A convert fp32 -> bf16 hi/lo, swizzled smem (overlaps cp.async) ----
#pragma unroll
    for (int i = 0; i < 16; ++i) {
        int idx = i * 256 + tid;            // 0..4095
        int r = idx >> 5, c4 = (idx & 31) * 4;
        int gr = row0 + r;
        float4 v = make_float4(0.f, 0.f, 0.f, 0.f);
        if (gr < N_ENT)   v = *(const float4*)(ent + (size_t)gr * D + c4);
        else if (gr < NT) v = *(const float4*)(qry + (size_t)(gr - N_ENT) * D + c4);
        float f[4] = {v.x, v.y, v.z, v.w};
        uint32_t h01 = 0, h23 = 0, l01 = 0, l23 = 0;
#pragma unroll
        for (int j = 0; j < 4; ++j) {
            __nv_bfloat16 hb = __float2bfloat16(f[j]);
            __nv_bfloat16 lb = __float2bfloat16(f[j] - __bfloat162float(hb));
            uint32_t hu = *(unsigned short*)&hb, lu = *(unsigned short*)&lb;
            if (j < 2) { h01 |= hu << (16 * j);       l01 |= lu << (16 * j); }
            else       { h23 |= hu << (16 * (j - 2)); l23 |= lu << (16 * (j - 2)); }
        }
        uint32_t off = (uint32_t)(r * 256 + (((c4 >> 3) ^ (r & 7)) << 4) + ((c4 & 4) ? 8 : 0));
        *(uint2*)(smem + SM_AHI + off) = make_uint2(h01, h23);
        *(uint2*)(smem + SM_ALO + off) = make_uint2(l01, l23);
    }

    const int wm = wid & 3;     // 4 m-groups of 32 rows
    const int wn = wid >> 2;    // 2 n-groups of 64 cols
    const int am = wm * 32 + (lane & 15);
    const int akc = (lane >> 4);
    const int bn = wn * 64 + ((lane >> 4) & 1) * 8 + (lane & 7);
    const int bkc = ((lane >> 3) & 1);
    const int gid = lane >> 2, tig = lane & 3;
    const uint32_t a0base = sb + SM_AHI + (uint32_t)(am * 256);
    const uint32_t a1base = sb + SM_AHI + (uint32_t)((am + 16) * 256);
    const int axor = am & 7;
    const uint32_t bbase = sb + SM_B + (uint32_t)(bn * 256);

    for (int t = 0; t < 4; ++t) {
        CPWAIT();              // Bh(t) arrived
        __syncthreads();       // (first iter: also covers A convert)

        float acc[2][8][4];
#pragma unroll
        for (int a = 0; a < 2; ++a)
#pragma unroll
            for (int b = 0; b < 8; ++b)
#pragma unroll
                for (int c = 0; c < 4; ++c) acc[a][b][c] = 0.f;

        // ---- phase 1: Ah*Bh + Al*Bh ----
#pragma unroll
        for (int ks = 0; ks < 8; ++ks) {
            uint32_t ach = (uint32_t)(((2 * ks + akc) ^ axor) << 4);
            uint32_t ah0[4], ah1[4], al0[4], al1[4];
            ldsm_x4(ah0, a0base + ach);
            ldsm_x4(al0, a0base + ach + PLANE);
            ldsm_x4(ah1, a1base + ach);
            ldsm_x4(al1, a1base + ach + PLANE);
#pragma unroll
            for (int ntp = 0; ntp < 4; ++ntp) {
                uint32_t baddr = bbase + (uint32_t)(ntp * 16 * 256 + (((2 * ks + bkc) ^ ((bn + ntp * 16) & 7)) << 4));
                uint32_t bh[4];
                ldsm_x4(bh, baddr);
                mma_bf16(acc[0][2 * ntp],     ah0, bh);
                mma_bf16(acc[0][2 * ntp],     al0, bh);
                mma_bf16(acc[0][2 * ntp + 1], ah0, bh + 2);
                mma_bf16(acc[0][2 * ntp + 1], al0, bh + 2);
                mma_bf16(acc[1][2 * ntp],     ah1, bh);
                mma_bf16(acc[1][2 * ntp],     al1, bh);
                mma_bf16(acc[1][2 * ntp + 1], ah1, bh + 2);
                mma_bf16(acc[1][2 * ntp + 1], al1, bh + 2);
            }
        }
        __syncthreads();

        // ---- phase 2: Ah*Bl ----
        load_b_tile(sb, g_wl + (size_t)t * 16384, tid);
        CPWAIT();
        __syncthreads();
#pragma unroll
        for (int ks = 0; ks < 8; ++ks) {
            uint32_t ach = (uint32_t)(((2 * ks + akc) ^ axor) << 4);
            uint32_t ah0[4], ah1[4];
            ldsm_x4(ah0, a0base + ach);
            ldsm_x4(ah1, a1base + ach);
#pragma unroll
            for (int ntp = 0; ntp < 4; ++ntp) {
                uint32_t baddr = bbase + (uint32_t)(ntp * 16 * 256 + (((2 * ks + bkc) ^ ((bn + ntp * 16) & 7)) << 4));
                uint32_t blo[4];
                ldsm_x4(blo, baddr);
                mma_bf16(acc[0][2 * ntp],     ah0, blo);
                mma_bf16(acc[0][2 * ntp + 1], ah0, blo + 2);
                mma_bf16(acc[1][2 * ntp],     ah1, blo);
                mma_bf16(acc[1][2 * ntp + 1], ah1, blo + 2);
            }
        }
        __syncthreads();
        if (t < 3) load_b_tile(sb, g_wh + (size_t)(t + 1) * 16384, tid);  // overlap epilogue

        // ---- epilogue: fp16-only stores ----
#pragma unroll
        for (int mi = 0; mi < 2; ++mi) {
            int r1 = row0 + wm * 32 + mi * 16 + gid;
            int r2 = r1 + 8;
#pragma unroll
            for (int ni = 0; ni < 8; ++ni) {
                int cg = t * 128 + wn * 64 + ni * 8 + tig * 2;   // 0..511
                __half* base;
                const float* bb;
                int c;
                if (cg < HD) { base = g_xlh; c = cg;      bb = bl; }
                else         { base = g_xr;  c = cg - HD; bb = br; }
                float2 bv = *(const float2*)(bb + c);
                if (r1 < NT)
                    *(__half2*)(base + (size_t)r1 * HD + c) =
                        __floats2half2_rn(acc[mi][ni][0] + bv.x, acc[mi][ni][1] + bv.y);
                if (r2 < NT)
                    *(__half2*)(base + (size_t)r2 * HD + c) =
                        __floats2half2_rn(acc[mi][ni][2] + bv.x, acc[mi][ni][3] + bv.y);
            }
        }
    }
}

// ---------------- init ----------------
__global__ void k_init(float* __restrict__ out, const float* __restrict__ bias) {
    int i = blockIdx.x * blockDim.x + threadIdx.x;
    if (i < N_ENT * D) out[i] = bias[i & (D - 1)];
    if (i < N_ENT * 2) g_den[i] = 0.f;
}

// ---------------- fused: e_rel = rel_feat @ W_ea.T, out_edge row ----------------
__global__ void k_rel_fused(const float* __restrict__ relations, const float* __restrict__ Wea,
                            const float* __restrict__ Wle, const float* __restrict__ ble,
                            float* __restrict__ out) {
    __shared__ float row[D];
    __shared__ float hid[HD];
    __shared__ float part[256];
    int r = blockIdx.x;          // 0..500
    int tid = threadIdx.x;       // 256
    if (tid < D) row[tid] = (r == R_REL) ? 1.f : relations[r * D + tid];
    __syncthreads();
    const float4* rv = (const float4*)row;
    const float4* wv = (const float4*)(Wea + (size_t)tid * D);
    float s = 0.f;
#pragma unroll
    for (int k = 0; k < D / 4; ++k) {
        float4 a = rv[k], b = wv[k];
        s += a.x * b.x + a.y * b.y + a.z * b.z + a.w * b.w;
    }
    g_erel[r * HD + tid] = __float2half(s);
    if (r == R_REL) return;
    hid[tid] = fmaxf(s, 0.f);
    __syncthreads();

    int col = tid & 127, half = tid >> 7;
    const float4* hv = (const float4*)(hid + half * 128);
    const float4* wlv = (const float4*)(Wle + (size_t)col * HD + half * 128);
    float p = 0.f;
#pragma unroll
    for (int k = 0; k < 32; ++k) {
        float4 a = hv[k], b = wlv[k];
        p += a.x * b.x + a.y * b.y + a.z * b.z + a.w * b.w;
    }
    part[tid] = p;
    __syncthreads();
    if (tid < 128)
        out[(size_t)N_ENT * D + r * D + tid] = part[tid] + part[tid + 128] + ble[tid];
}

// ---------------- edge helpers ----------------
__device__ __forceinline__ void edge_st(int gw, const int* __restrict__ ei,
                                        const int* __restrict__ batch, int& s, int& t) {
    if (gw < E_EDGE) { s = ei[gw]; t = ei[E_EDGE + gw]; }
    else             { int i = gw - E_EDGE; s = N_ENT + batch[i]; t = i; }
}
__device__ __forceinline__ float4 leaky4(float4 z) {
    z.x = z.x > 0.f ? z.x : NEG * z.x;
    z.y = z.y > 0.f ? z.y : NEG * z.y;
    z.z = z.z > 0.f ? z.z : NEG * z.z;
    z.w = z.w > 0.f ? z.w : NEG * z.w;
    return z;
}
__device__ __forceinline__ float4 h4_to_f4(uint2 u) {
    __half2* hp = (__half2*)&u;
    float2 a = __half22float2(hp[0]), b = __half22float2(hp[1]);
    return make_float4(a.x, a.y, b.x, b.y);
}

// ---------------- edge pass 1: logits (fp16 gathers) ----------------
__global__ void k_logits(const int* __restrict__ ei, const int* __restrict__ ridx,
                         const int* __restrict__ batch, const float* __restrict__ att) {
    int gw = (blockIdx.x * blockDim.x + threadIdx.x) >> 5;
    if (gw >= E_TOT) return;
    int lane = threadIdx.x & 31;
    int s, t;
    edge_st(gw, ei, batch, s, t);
    int rel = (gw < E_EDGE) ? ridx[gw] : R_REL;

    const uint2*  A  = (const uint2*)g_xlh + (size_t)s * 64;
    const uint2*  Xr = (const uint2*)g_xr + (size_t)t * 64;
    const uint2*  Ee = (const uint2*)g_erel + (size_t)rel * 64;
    const float4* At = (const float4*)att;

    float4 a = h4_to_f4(A[lane]);
    float4 b = h4_to_f4(Xr[lane]);
    float4 c = h4_to_f4(Ee[lane]);
    float4 z = leaky4(make_float4(a.x + b.x + c.x, a.y + b.y + c.y,
                                  a.z + b.z + c.z, a.w + b.w + c.w));
    float4 ta = At[lane];
    float s0 = z.x * ta.x + z.y * ta.y + z.z * ta.z + z.w * ta.w;

    a = h4_to_f4(A[lane + 32]);
    b = h4_to_f4(Xr[lane + 32]);
    c = h4_to_f4(Ee[lane + 32]);
    z = leaky4(make_float4(a.x + b.x + c.x, a.y + b.y + c.y,
                           a.z + b.z + c.z, a.w + b.w + c.w));
    ta = At[lane + 32];
    float s1 = z.x * ta.x + z.y * ta.y + z.z * ta.z + z.w * ta.w;

#pragma unroll
    for (int o = 16; o; o >>= 1) {
        s0 += __shfl_xor_sync(0xffffffffu, s0, o);
        s1 += __shfl_xor_sync(0xffffffffu, s1, o);
    }
    if (lane == 0) {
        float2 pv;
        pv.x = expf(s0);
        pv.y = expf(s1);
        ((float2*)g_p)[gw] = pv;
        atomicAdd((float2*)g_den + t, pv);
    }
}

// ---------------- edge pass 2: aggregation (fp16 value gather, fp32 atomics) ---
__global__ void k_agg(const int* __restrict__ ei, const int* __restrict__ batch,
                      float* __restrict__ out) {
    int gw = (blockIdx.x * blockDim.x + threadIdx.x) >> 5;
    if (gw >= E_TOT) return;
    int lane = threadIdx.x & 31;
    int s, t;
    edge_st(gw, ei, batch, s, t);

    float2 p  = ((const float2*)g_p)[gw];
    float2 dn = ((const float2*)g_den)[t];
    float w0 = 0.5f * p.x / (dn.x + 1e-16f);
    float w1 = 0.5f * p.y / (dn.y + 1e-16f);

    const uint2* A = (const uint2*)g_xlh + (size_t)s * 64;
    float4 a0 = h4_to_f4(A[lane]), a1 = h4_to_f4(A[lane + 32]);
    float4 v = make_float4(w0 * a0.x + w1 * a1.x, w0 * a0.y + w1 * a1.y,
                           w0 * a0.z + w1 * a1.z, w0 * a0.w + w1 * a1.w);
    atomicAdd((float4*)out + (size_t)t * 32 + lane, v);
}

// ---------------- launch ----------------
extern "C" void kernel_launch(void* const* d_in, const int* in_sizes, int n_in,
                              void* d_out, int out_size) {
    const float* queries        = (const float*)d_in[0];
    const float* entities       = (const float*)d_in[1];
    const int*   edge_index     = (const int*)d_in[2];
    const float* relations      = (const float*)d_in[3];
    const int*   relation_index = (const int*)d_in[4];
    const int*   batch          = (const int*)d_in[5];
    const float* W_l  = (const float*)d_in[6];
    const float* b_l  = (const float*)d_in[7];
    const float* W_r  = (const float*)d_in[8];
    const float* b_r  = (const float*)d_in[9];
    const float* W_ea = (const float*)d_in[10];
    const float* att  = (const float*)d_in[11];
    const float* bias = (const float*)d_in[12];
    const float* W_le = (const float*)d_in[13];
    const float* b_le = (const float*)d_in[14];
    float* out = (float*)d_out;

    k_wsplit<<<(512 * 128 + 255) / 256, 256>>>(W_l, W_r);
    k_init<<<(N_ENT * D + 255) / 256, 256>>>(out, bias);
    k_rel_fused<<<R_REL + 1, 256>>>(relations, W_ea, W_le, b_le, out);

    cudaFuncSetAttribute(k_gemm_mma, cudaFuncAttributeMaxDynamicSharedMemorySize, SM_TOTAL);
    k_gemm_mma<<<(NT + 127) / 128, 256, SM_TOTAL>>>(entities, queries, b_l, b_r);

    int edge_blocks = (E_TOT * 32 + 255) / 256;
    k_logits<<<edge_blocks, 256>>>(edge_index, relation_index, batch, att);
    k_agg<<<edge_blocks, 256>>>(edge_index, batch, out);
}

// round 8
// speedup vs baseline: 1.1460x; 1.0031x over previous
#include <cuda_runtime.h>
#include <cuda_bf16.h>
#include <cuda_fp16.h>
#include <cstdint>

#define N_ENT  100000
#define NQ     64
#define NT     100064
#define D      128
#define HD     256
#define E_EDGE 400000
#define E_TOT  500000
#define R_REL  500
#define NEG    0.2f

// ---------------- static device scratch ----------------
// All feature rows stored HEAD-INTERLEAVED: index j = d*2 + h  (h in {0,1})
__device__ __align__(16) __half g_xlh[(size_t)NT * HD];     // fp16 x_l interleaved
__device__ __align__(16) __half g_xr[(size_t)NT * HD];      // fp16 x_r interleaved
__device__ __align__(16) __half g_erel[(R_REL + 1) * HD];   // fp16 e_rel interleaved
__device__ __align__(16) float  g_atti[HD];                 // att interleaved
__device__ float g_p[(size_t)E_TOT * 2];
__device__ float g_den[(size_t)N_ENT * 2];
__device__ __nv_bfloat16 g_wh[512 * 128];   // permuted [outcol n][k] bf16 hi
__device__ __nv_bfloat16 g_wl[512 * 128];   // bf16 lo residual

// ---------------- helpers ----------------
__device__ __forceinline__ uint32_t smem_u32(const void* p) {
    uint32_t a;
    asm("{ .reg .u64 t; cvta.to.shared.u64 t, %1; cvt.u32.u64 %0, t; }" : "=r"(a) : "l"(p));
    return a;
}
__device__ __forceinline__ void ldsm_x4(uint32_t* r, uint32_t addr) {
    asm volatile("ldmatrix.sync.aligned.m8n8.x4.shared.b16 {%0,%1,%2,%3}, [%4];"
                 : "=r"(r[0]), "=r"(r[1]), "=r"(r[2]), "=r"(r[3]) : "r"(addr));
}
__device__ __forceinline__ void mma_bf16(float* d, const uint32_t* a, const uint32_t* b) {
    asm volatile("mma.sync.aligned.m16n8k16.row.col.f32.bf16.bf16.f32 "
                 "{%0,%1,%2,%3}, {%4,%5,%6,%7}, {%8,%9}, {%0,%1,%2,%3};"
                 : "+f"(d[0]), "+f"(d[1]), "+f"(d[2]), "+f"(d[3])
                 : "r"(a[0]), "r"(a[1]), "r"(a[2]), "r"(a[3]), "r"(b[0]), "r"(b[1]));
}
__device__ __forceinline__ void cp16(uint32_t dst, const void* src) {
    asm volatile("cp.async.cg.shared.global [%0], [%1], 16;" :: "r"(dst), "l"(src));
}

// XOR-swizzled planes, 256B rows: plane = 32KB
#define PLANE 32768
#define SM_AHI 0
#define SM_ALO PLANE
#define SM_B   (2 * PLANE)
#define SM_TOTAL (3 * PLANE)        // 98304 -> 2 CTAs/SM

// ---------------- split W into bf16 hi/lo (interleave permutation) ----------------
// GEMM output col n gets original col perm(n) = (n&1)*128 + (n>>1) within its half.
__global__ void k_wsplit(const float* __restrict__ Wl, const float* __restrict__ Wr) {
    int i = blockIdx.x * 256 + threadIdx.x;
    if (i >= 512 * 128) return;
    int n = i >> 7, k = i & 127;
    float v;
    if (n < 256) { int m = (n & 1) * 128 + (n >> 1); v = Wl[m * 128 + k]; }
    else         { int q = n - 256; int m = (q & 1) * 128 + (q >> 1); v = Wr[m * 128 + k]; }
    __nv_bfloat16 h = __float2bfloat16(v);
    g_wh[i] = h;
    g_wl[i] = __float2bfloat16(v - __bfloat162float(h));
}

// B tile loader: 128 n-rows x 128 k bf16, 16B chunks, swizzled (256 threads)
__device__ __forceinline__ void load_b_tile(uint32_t sb, const __nv_bfloat16* w, int tid) {
#pragma unroll
    for (int i = 0; i < 8; ++i) {
        int j = i * 256 + tid;          // 0..2047
        int r = j >> 4, c = j & 15;
        uint32_t dst = sb + SM_B + (uint32_t)(r * 256 + ((c ^ (r & 7)) << 4));
        cp16(dst, w + r * 128 + c * 8);
    }
    asm volatile("cp.async.commit_group;" ::: "memory");
}
#define CPWAIT() asm volatile("cp.async.wait_group 0;" ::: "memory")

// ---------------- HMMA GEMM: interleaved [x_l|x_r] = node @ Wperm.T + bias -------
__global__ __launch_bounds__(256, 2) void k_gemm_mma(
    const float* __restrict__ ent, const float* __restrict__ qry,
    const float* __restrict__ bl, const float* __restrict__ br) {
    extern __shared__ char smem[];
    const uint32_t sb = smem_u32(smem);
    const int tid = threadIdx.x;
    const int wid = tid >> 5, lane = tid & 31;
    const int row0 = blockIdx.x * 128;

    load_b_tile(sb, g_wh, tid);      // prefetch Bh(0)

    // ---- A convert fp32 -> bf16 hi/lo, swizzled smem (overlaps cp.async) ----
#pragma unroll
    for (int i = 0; i < 16; ++i) {
        int idx = i * 256 + tid;            // 0..4095
        int r = idx >> 5, c4 = (idx & 31) * 4;
        int gr = row0 + r;
        float4 v = make_float4(0.f, 0.f, 0.f, 0.f);
        if (gr < N_ENT)   v = *(const float4*)(ent + (size_t)gr * D + c4);
        else if (gr < NT) v = *(const float4*)(qry + (size_t)(gr - N_ENT) * D + c4);
        float f[4] = {v.x, v.y, v.z, v.w};
        uint32_t h01 = 0, h23 = 0, l01 = 0, l23 = 0;
#pragma unroll
        for (int j = 0; j < 4; ++j) {
            __nv_bfloat16 hb = __float2bfloat16(f[j]);
            __nv_bfloat16 lb = __float2bfloat16(f[j] - __bfloat162float(hb));
            uint32_t hu = *(unsigned short*)&hb, lu = *(unsigned short*)&lb;
            if (j < 2) { h01 |= hu << (16 * j);       l01 |= lu << (16 * j); }
            else       { h23 |= hu << (16 * (j - 2)); l23 |= lu << (16 * (j - 2)); }
        }
        uint32_t off = (uint32_t)(r * 256 + (((c4 >> 3) ^ (r & 7)) << 4) + ((c4 & 4) ? 8 : 0));
        *(uint2*)(smem + SM_AHI + off) = make_uint2(h01, h23);
        *(uint2*)(smem + SM_ALO + off) = make_uint2(l01, l23);
    }

    const int wm = wid & 3;     // 4 m-groups of 32 rows
    const int wn = wid >> 2;    // 2 n-groups of 64 cols
    const int am = wm * 32 + (lane & 15);
    const int akc = (lane >> 4);
    const int bn = wn * 64 + ((lane >> 4) & 1) * 8 + (lane & 7);
    const int bkc = ((lane >> 3) & 1);
    const int gid = lane >> 2, tig = lane & 3;
    const uint32_t a0base = sb + SM_AHI + (uint32_t)(am * 256);
    const uint32_t a1base = sb + SM_AHI + (uint32_t)((am + 16) * 256);
    const int axor = am & 7;
    const uint32_t bbase = sb + SM_B + (uint32_t)(bn * 256);

    for (int t = 0; t < 4; ++t) {
        CPWAIT();              // Bh(t) arrived
        __syncthreads();       // (first iter: also covers A convert)

        float acc[2][8][4];
#pragma unroll
        for (int a = 0; a < 2; ++a)
#pragma unroll
            for (int b = 0; b < 8; ++b)
#pragma unroll
                for (int c = 0; c < 4; ++c) acc[a][b][c] = 0.f;

        // ---- phase 1: Ah*Bh + Al*Bh ----
#pragma unroll
        for (int ks = 0; ks < 8; ++ks) {
            uint32_t ach = (uint32_t)(((2 * ks + akc) ^ axor) << 4);
            uint32_t ah0[4], ah1[4], al0[4], al1[4];
            ldsm_x4(ah0, a0base + ach);
            ldsm_x4(al0, a0base + ach + PLANE);
            ldsm_x4(ah1, a1base + ach);
            ldsm_x4(al1, a1base + ach + PLANE);
#pragma unroll
            for (int ntp = 0; ntp < 4; ++ntp) {
                uint32_t baddr = bbase + (uint32_t)(ntp * 16 * 256 + (((2 * ks + bkc) ^ ((bn + ntp * 16) & 7)) << 4));
                uint32_t bh[4];
                ldsm_x4(bh, baddr);
                mma_bf16(acc[0][2 * ntp],     ah0, bh);
                mma_bf16(acc[0][2 * ntp],     al0, bh);
                mma_bf16(acc[0][2 * ntp + 1], ah0, bh + 2);
                mma_bf16(acc[0][2 * ntp + 1], al0, bh + 2);
                mma_bf16(acc[1][2 * ntp],     ah1, bh);
                mma_bf16(acc[1][2 * ntp],     al1, bh);
                mma_bf16(acc[1][2 * ntp + 1], ah1, bh + 2);
                mma_bf16(acc[1][2 * ntp + 1], al1, bh + 2);
            }
        }
        __syncthreads();

        // ---- phase 2: Ah*Bl ----
        load_b_tile(sb, g_wl + (size_t)t * 16384, tid);
        CPWAIT();
        __syncthreads();
#pragma unroll
        for (int ks = 0; ks < 8; ++ks) {
            uint32_t ach = (uint32_t)(((2 * ks + akc) ^ axor) << 4);
            uint32_t ah0[4], ah1[4];
            ldsm_x4(ah0, a0base + ach);
            ldsm_x4(ah1, a1base + ach);
#pragma unroll
            for (int ntp = 0; ntp < 4; ++ntp) {
                uint32_t baddr = bbase + (uint32_t)(ntp * 16 * 256 + (((2 * ks + bkc) ^ ((bn + ntp * 16) & 7)) << 4));
                uint32_t blo[4];
                ldsm_x4(blo, baddr);
                mma_bf16(acc[0][2 * ntp],     ah0, blo);
                mma_bf16(acc[0][2 * ntp + 1], ah0, blo + 2);
                mma_bf16(acc[1][2 * ntp],     ah1, blo);
                mma_bf16(acc[1][2 * ntp + 1], ah1, blo + 2);
            }
        }
        __syncthreads();
        if (t < 3) load_b_tile(sb, g_wh + (size_t)(t + 1) * 16384, tid);  // overlap epilogue

        // ---- epilogue: fp16 stores; bias via interleave index ----
#pragma unroll
        for (int mi = 0; mi < 2; ++mi) {
            int r1 = row0 + wm * 32 + mi * 16 + gid;
            int r2 = r1 + 8;
#pragma unroll
            for (int ni = 0; ni < 8; ++ni) {
                int cg = t * 128 + wn * 64 + ni * 8 + tig * 2;   // even, 0..510
                __half* base;
                const float* bb;
                int c;
                if (cg < HD) { base = g_xlh; c = cg;      bb = bl; }
                else         { base = g_xr;  c = cg - HD; bb = br; }
                int d = c >> 1;                  // pair (c, c+1) = (h0 d, h1 d)
                float bvx = bb[d], bvy = bb[128 + d];
                if (r1 < NT)
                    *(__half2*)(base + (size_t)r1 * HD + c) =
                        __floats2half2_rn(acc[mi][ni][0] + bvx, acc[mi][ni][1] + bvy);
                if (r2 < NT)
                    *(__half2*)(base + (size_t)r2 * HD + c) =
                        __floats2half2_rn(acc[mi][ni][2] + bvx, acc[mi][ni][3] + bvy);
            }
        }
    }
}

// ---------------- init ----------------
__global__ void k_init(float* __restrict__ out, const float* __restrict__ bias,
                       const float* __restrict__ att) {
    int i = blockIdx.x * blockDim.x + threadIdx.x;
    if (i < N_ENT * D) out[i] = bias[i & (D - 1)];
    if (i < N_ENT * 2) g_den[i] = 0.f;
    if (i < HD) g_atti[(i & 127) * 2 + (i >> 7)] = att[i];
}

// ---------------- fused: e_rel (interleaved) + out_edge row ----------------
__global__ void k_rel_fused(const float* __restrict__ relations, const float* __restrict__ Wea,
                            const float* __restrict__ Wle, const float* __restrict__ ble,
                            float* __restrict__ out) {
    __shared__ float row[D];
    __shared__ float hid[HD];
    __shared__ float part[256];
    int r = blockIdx.x;          // 0..500
    int tid = threadIdx.x;       // 256
    if (tid < D) row[tid] = (r == R_REL) ? 1.f : relations[r * D + tid];
    __syncthreads();
    const float4* rv = (const float4*)row;
    const float4* wv = (const float4*)(Wea + (size_t)tid * D);
    float s = 0.f;
#pragma unroll
    for (int k = 0; k < D / 4; ++k) {
        float4 a = rv[k], b = wv[k];
        s += a.x * b.x + a.y * b.y + a.z * b.z + a.w * b.w;
    }
    g_erel[r * HD + (tid & 127) * 2 + (tid >> 7)] = __float2half(s);
    if (r == R_REL) return;
    hid[tid] = fmaxf(s, 0.f);
    __syncthreads();

    int col = tid & 127, half = tid >> 7;
    const float4* hv = (const float4*)(hid + half * 128);
    const float4* wlv = (const float4*)(Wle + (size_t)col * HD + half * 128);
    float p = 0.f;
#pragma unroll
    for (int k = 0; k < 32; ++k) {
        float4 a = hv[k], b = wlv[k];
        p += a.x * b.x + a.y * b.y + a.z * b.z + a.w * b.w;
    }
    part[tid] = p;
    __syncthreads();
    if (tid < 128)
        out[(size_t)N_ENT * D + r * D + tid] = part[tid] + part[tid + 128] + ble[tid];
}

// ---------------- edge helpers ----------------
__device__ __forceinline__ void edge_st(int gw, const int* __restrict__ ei,
                                        const int* __restrict__ batch, int& s, int& t) {
    if (gw < E_EDGE) { s = ei[gw]; t = ei[E_EDGE + gw]; }
    else             { int i = gw - E_EDGE; s = N_ENT + batch[i]; t = i; }
}

// ---------------- edge pass 1: logits (one uint4 gather per table per lane) ----
__global__ void k_logits(const int* __restrict__ ei, const int* __restrict__ ridx,
                         const int* __restrict__ batch) {
    int gw = (blockIdx.x * blockDim.x + threadIdx.x) >> 5;
    if (gw >= E_TOT) return;
    int lane = threadIdx.x & 31;
    int s, t;
    edge_st(gw, ei, batch, s, t);
    int rel = (gw < E_EDGE) ? ridx[gw] : R_REL;

    uint4 av = ((const uint4*)g_xlh)[(size_t)s * 32 + lane];
    uint4 bv = ((const uint4*)g_xr)[(size_t)t * 32 + lane];
    uint4 cv = ((const uint4*)g_erel)[(size_t)rel * 32 + lane];
    float4 at0 = ((const float4*)g_atti)[lane * 2];
    float4 at1 = ((const float4*)g_atti)[lane * 2 + 1];
    const float* atp = (const float*)&at0;   // att_int[8*lane .. +7]

    const uint32_t* au = (const uint32_t*)&av;
    const uint32_t* bu = (const uint32_t*)&bv;
    const uint32_t* cu = (const uint32_t*)&cv;

    float s0 = 0.f, s1 = 0.f;
#pragma unroll
    for (int k = 0; k < 4; ++k) {
        float2 a = __half22float2(*(const __half2*)&au[k]);
        float2 b = __half22float2(*(const __half2*)&bu[k]);
        float2 c = __half22float2(*(const __half2*)&cu[k]);
        float z0 = a.x + b.x + c.x;
        float z1 = a.y + b.y + c.y;
        z0 = z0 > 0.f ? z0 : NEG * z0;
        z1 = z1 > 0.f ? z1 : NEG * z1;
        float aw0 = (k < 2) ? ((const float*)&at0)[2 * k]     : ((const float*)&at1)[2 * (k - 2)];
        float aw1 = (k < 2) ? ((const float*)&at0)[2 * k + 1] : ((const float*)&at1)[2 * (k - 2) + 1];
        s0 += z0 * aw0;     // even = head0
        s1 += z1 * aw1;     // odd = head1
    }
    (void)atp;
#pragma unroll
    for (int o = 16; o; o >>= 1) {
        s0 += __shfl_xor_sync(0xffffffffu, s0, o);
        s1 += __shfl_xor_sync(0xffffffffu, s1, o);
    }
    if (lane == 0) {
        float2 pv;
        pv.x = expf(s0);
        pv.y = expf(s1);
        ((float2*)g_p)[gw] = pv;
        atomicAdd((float2*)g_den + t, pv);
    }
}

// ---------------- edge pass 2: aggregation (one uint4 gather + one RED per lane)
__global__ void k_agg(const int* __restrict__ ei, const int* __restrict__ batch,
                      float* __restrict__ out) {
    int gw = (blockIdx.x * blockDim.x + threadIdx.x) >> 5;
    if (gw >= E_TOT) return;
    int lane = threadIdx.x & 31;
    int s, t;
    edge_st(gw, ei, batch, s, t);

    float2 p  = ((const float2*)g_p)[gw];
    float2 dn = ((const float2*)g_den)[t];
    float w0 = 0.5f * p.x / (dn.x + 1e-16f);
    float w1 = 0.5f * p.y / (dn.y + 1e-16f);

    uint4 av = ((const uint4*)g_xlh)[(size_t)s * 32 + lane];   // cols 4l..4l+3, both heads
    const uint32_t* au = (const uint32_t*)&av;
    float v[4];
#pragma unroll
    for (int k = 0; k < 4; ++k) {
        float2 a = __half22float2(*(const __half2*)&au[k]);
        v[k] = w0 * a.x + w1 * a.y;
    }
    atomicAdd((float4*)out + (size_t)t * 32 + lane, make_float4(v[0], v[1], v[2], v[3]));
}

// ---------------- launch ----------------
extern "C" void kernel_launch(void* const* d_in, const int* in_sizes, int n_in,
                              void* d_out, int out_size) {
    const float* queries        = (const float*)d_in[0];
    const float* entities       = (const float*)d_in[1];
    const int*   edge_index     = (const int*)d_in[2];
    const float* relations      = (const float*)d_in[3];
    const int*   relation_index = (const int*)d_in[4];
    const int*   batch          = (const int*)d_in[5];
    const float* W_l  = (const float*)d_in[6];
    const float* b_l  = (const float*)d_in[7];
    const float* W_r  = (const float*)d_in[8];
    const float* b_r  = (const float*)d_in[9];
    const float* W_ea = (const float*)d_in[10];
    const float* att  = (const float*)d_in[11];
    const float* bias = (const float*)d_in[12];
    const float* W_le = (const float*)d_in[13];
    const float* b_le = (const float*)d_in[14];
    float* out = (float*)d_out;

    k_wsplit<<<(512 * 128 + 255) / 256, 256>>>(W_l, W_r);
    k_init<<<(N_ENT * D + 255) / 256, 256>>>(out, bias, att);
    k_rel_fused<<<R_REL + 1, 256>>>(relations, W_ea, W_le, b_le, out);

    cudaFuncSetAttribute(k_gemm_mma, cudaFuncAttributeMaxDynamicSharedMemorySize, SM_TOTAL);
    k_gemm_mma<<<(NT + 127) / 128, 256, SM_TOTAL>>>(entities, queries, b_l, b_r);

    int edge_blocks = (E_TOT * 32 + 255) / 256;
    k_logits<<<edge_blocks, 256>>>(edge_index, relation_index, batch);
    k_agg<<<edge_blocks, 256>>>(edge_index, batch, out);
}